// round 16
// baseline (speedup 1.0000x reference)
#include <cuda_runtime.h>
#include <cuda_fp16.h>
#include <cstdint>
#include <math.h>

// Problem constants
#define NB 8
#define NL 384
#define ND 1024
#define NE 4
#define NH 4096
#define MTOT (NB * NL)   // 3072 tokens

// ---------------------------------------------------------------------------
// Device scratch (static; no runtime allocation)
// ---------------------------------------------------------------------------
__device__ float g_w_be[NB * NE];
__device__ float g_gpart[NB][12][ND];

__device__ __align__(16) __half g_x16[(size_t)MTOT * ND];

// 5 h slabs (shared + 4 experts), fp16
__device__ __align__(16) __half g_h16[(size_t)5 * MTOT * NH];

// Expert GEMM2 weighted partials: 4 slices (one per expert), fp16
__device__ __align__(16) __half g_parteh[(size_t)4 * MTOT * ND];

// Transposed weights fp16: W1T [5][4096][1024], W2T [5][1024][4096]
__device__ __align__(16) __half g_w1t[(size_t)5 * NH * ND];
__device__ __align__(16) __half g_w2t[(size_t)5 * ND * NH];

// ---------------------------------------------------------------------------
// PTX helpers (sm_80+ target-independent)
// ---------------------------------------------------------------------------
__device__ __forceinline__ uint32_t smem_to_u32(const void* p) {
    uint32_t a;
    asm("{ .reg .u64 t; cvta.to.shared.u64 t, %1; cvt.u32.u64 %0, t; }"
        : "=r"(a) : "l"(p));
    return a;
}
__device__ __forceinline__ void cp_async16(uint32_t dst, const void* src) {
    asm volatile("cp.async.cg.shared.global [%0], [%1], 16;"
                 :: "r"(dst), "l"(src));
}
#define CP_COMMIT() asm volatile("cp.async.commit_group;" ::: "memory")
#define CP_WAIT(n)  asm volatile("cp.async.wait_group %0;" :: "n"(n) : "memory")

#define LDSM_X4(r, addr) \
    asm volatile("ldmatrix.sync.aligned.m8n8.x4.shared.b16 {%0,%1,%2,%3}, [%4];" \
        : "=r"((r)[0]), "=r"((r)[1]), "=r"((r)[2]), "=r"((r)[3]) \
        : "r"(addr))

#define MMA_F16(d, a, b) \
    asm volatile("mma.sync.aligned.m16n8k16.row.col.f32.f16.f16.f32 " \
        "{%0,%1,%2,%3}, {%4,%5,%6,%7}, {%8,%9}, {%0,%1,%2,%3};" \
        : "+f"((d)[0]), "+f"((d)[1]), "+f"((d)[2]), "+f"((d)[3]) \
        : "r"((a)[0]), "r"((a)[1]), "r"((a)[2]), "r"((a)[3]), \
          "r"((b)[0]), "r"((b)[1]))

__device__ __forceinline__ float gelu_tanh(float x) {
    float x3 = x * x * x;
    return 0.5f * x * (1.0f + tanhf(0.7978845608028654f * (x + 0.044715f * x3)));
}
// 128B-row SMEM swizzle (Swizzle<3,4,3>): chunk16 ^= row&7
__device__ __forceinline__ uint32_t sw128(uint32_t off) {
    return off ^ ((off >> 3) & 0x70u);
}
__device__ __forceinline__ bool seg_masked(int e, int seg) {
    return (e == 1 && seg == 1) || (e == 2 && seg == 0);
}

// ---------------------------------------------------------------------------
// GEMM core (fp16 single-pass): 128x128 CTA, BK=64, 3-stage cp.async,
// 8 warps (4m x 2n), warp tile 32x64. Stage = A | B, 128x64 fp16 each
// (128B rows, SW128). 4 k16-steps per stage; one barrier per stage.
// ---------------------------------------------------------------------------
#define BM 128
#define BN 128
#define BK 64
#define SUB_BYTES 16384                   // 128 rows x 128B
#define STAGE_BYTES (2 * SUB_BYTES)       // 32KB
#define SMEM_GEMM (3 * STAGE_BYTES)       // 96KB

__device__ __forceinline__ void gemm_mainloop(
    const __half* __restrict__ A, const __half* __restrict__ B,
    int ldA, int ldB, int Klen,
    uint32_t sbase, int tid, float acc[2][8][4])
{
    const int wid  = tid >> 5;
    const int lane = tid & 31;
    const int wm   = wid >> 1;   // 0..3
    const int wn   = wid & 1;    // 0..1
    const int nc = Klen / BK;

    // loader: per subtile 128 rows x 8 chunks(16B) = 1024 chunks; 4/thread
    auto load_stage = [&](int kt, int s) {
        const uint32_t sb = sbase + s * STAGE_BYTES;
        #pragma unroll
        for (int t = 0; t < 2; t++) {
            const int ld = (t == 0) ? ldA : ldB;
            const __half* src = ((t == 0) ? A : B) + kt;
            #pragma unroll
            for (int i = 0; i < 4; i++) {
                int idx = tid + 256 * i;          // 0..1023
                int row = idx >> 3, ch = idx & 7;
                uint32_t off = sw128((uint32_t)(row * 128 + ch * 16));
                cp_async16(sb + t * SUB_BYTES + off,
                           src + (size_t)row * ld + ch * 8);
            }
        }
        CP_COMMIT();
    };

    // ldmatrix coords (row stride 128B)
    const int q = lane >> 3;
    const int a_row  = wm * 32 + (q & 1) * 8 + (lane & 7);
    const int a_colb = (q >> 1) * 16;
    const int b_row  = wn * 64 + (q >> 1) * 8 + (lane & 7);
    const int b_colb = (q & 1) * 16;

    uint32_t a_fr[2][4];
    auto ldsm_a = [&](int s, int ks) {
        const uint32_t sb = sbase + s * STAGE_BYTES;
        #pragma unroll
        for (int f = 0; f < 2; f++) {
            uint32_t off = sw128((uint32_t)((a_row + f * 16) * 128 + ks * 32 + a_colb));
            LDSM_X4(a_fr[f], sb + off);
        }
    };
    auto mma_b = [&](int s, int ks) {
        const uint32_t sb = sbase + s * STAGE_BYTES;
        #pragma unroll
        for (int g2 = 0; g2 < 4; g2++) {
            uint32_t off = sw128((uint32_t)((b_row + g2 * 16) * 128 + ks * 32 + b_colb));
            uint32_t rh[4];
            LDSM_X4(rh, sb + SUB_BYTES + off);
            uint32_t bh0[2] = {rh[0], rh[1]}, bh1[2] = {rh[2], rh[3]};
            MMA_F16(acc[0][2 * g2],     a_fr[0], bh0);
            MMA_F16(acc[0][2 * g2 + 1], a_fr[0], bh1);
            MMA_F16(acc[1][2 * g2],     a_fr[1], bh0);
            MMA_F16(acc[1][2 * g2 + 1], a_fr[1], bh1);
        }
    };

    load_stage(0, 0);
    load_stage(BK, 1);
    for (int c = 0; c < nc; c++) {
        if (c + 1 < nc) { CP_WAIT(1); } else { CP_WAIT(0); }
        __syncthreads();
        const int s = c % 3;
        ldsm_a(s, 0);
        if (c + 2 < nc) load_stage((c + 2) * BK, (c + 2) % 3);
        mma_b(s, 0);
        ldsm_a(s, 1);
        mma_b(s, 1);
        ldsm_a(s, 2);
        mma_b(s, 2);
        ldsm_a(s, 3);
        mma_b(s, 3);
    }
}

// ---------------------------------------------------------------------------
// GEMM1: grid (32, 24, nz), z = blockIdx.z + zoff. z=0 shared, z=e+1 expert.
// h[z] = gelu(x @ W1[z]^T + b1) -> fp16 slab.
// ---------------------------------------------------------------------------
__global__ __launch_bounds__(256, 2)
void gemm1_kernel(const float* __restrict__ sb1,
                  const float* __restrict__ eb1,
                  int zoff)
{
    const int z = blockIdx.z + zoff;
    const int mt = blockIdx.y;
    if (z > 0) {
        int e = z - 1, b = mt / 3, seg = mt % 3;
        if (seg_masked(e, seg)) return;
        if (g_w_be[b * NE + e] == 0.0f) return;
    }
    extern __shared__ char smem[];
    const uint32_t sbase = smem_to_u32(smem);
    const int tid = threadIdx.x;
    const int m0 = mt * BM;
    const int n0 = blockIdx.x * BN;

    const float* bias = (z == 0) ? sb1 : eb1 + (size_t)(z - 1) * NH;

    float acc[2][8][4];
    #pragma unroll
    for (int f = 0; f < 2; f++)
        #pragma unroll
        for (int g = 0; g < 8; g++)
            #pragma unroll
            for (int k = 0; k < 4; k++) acc[f][g][k] = 0.0f;

    gemm_mainloop(g_x16 + (size_t)m0 * ND,
                  g_w1t + (size_t)z * NH * ND + (size_t)n0 * ND,
                  ND, ND, ND, sbase, tid, acc);

    const int wid = tid >> 5, lane = tid & 31;
    const int wm = wid >> 1, wn = wid & 1;
    const int gid = lane >> 2, tig = lane & 3;
    __half* C = g_h16 + (size_t)z * MTOT * NH;
    #pragma unroll
    for (int f = 0; f < 2; f++) {
        #pragma unroll
        for (int g = 0; g < 8; g++) {
            const int col = n0 + wn * 64 + g * 8 + 2 * tig;
            const float2 bv = *(const float2*)(bias + col);
            #pragma unroll
            for (int half = 0; half < 2; half++) {
                const int row = m0 + wm * 32 + f * 16 + gid + half * 8;
                float v0 = gelu_tanh(acc[f][g][2 * half]     + bv.x);
                float v1 = gelu_tanh(acc[f][g][2 * half + 1] + bv.y);
                size_t o = ((size_t)row * NH + col) >> 1;
                ((__half2*)C)[o] = __halves2half2(__float2half(v0),
                                                  __float2half(v1));
            }
        }
    }
}

// ---------------------------------------------------------------------------
// GEMM2 shared path: grid (8, 24). Full K=4096.
// out = h[0] @ W2[0]^T + sb2   (direct fp32 write, no partial round-trip)
// ---------------------------------------------------------------------------
__global__ __launch_bounds__(256, 2)
void gemm2s_kernel(float* __restrict__ out, const float* __restrict__ sb2)
{
    extern __shared__ char smem[];
    const uint32_t sbase = smem_to_u32(smem);
    const int tid = threadIdx.x;
    const int m0 = blockIdx.y * BM;
    const int n0 = blockIdx.x * BN;

    float acc[2][8][4];
    #pragma unroll
    for (int f = 0; f < 2; f++)
        #pragma unroll
        for (int g = 0; g < 8; g++)
            #pragma unroll
            for (int k = 0; k < 4; k++) acc[f][g][k] = 0.0f;

    gemm_mainloop(g_h16 + (size_t)m0 * NH,
                  g_w2t + (size_t)n0 * NH,
                  NH, NH, NH, sbase, tid, acc);

    const int wid = tid >> 5, lane = tid & 31;
    const int wm = wid >> 1, wn = wid & 1;
    const int gid = lane >> 2, tig = lane & 3;
    #pragma unroll
    for (int f = 0; f < 2; f++) {
        #pragma unroll
        for (int g = 0; g < 8; g++) {
            const int col = n0 + wn * 64 + g * 8 + 2 * tig;
            const float2 bv = *(const float2*)(sb2 + col);
            #pragma unroll
            for (int half = 0; half < 2; half++) {
                const int row = m0 + wm * 32 + f * 16 + gid + half * 8;
                *(float2*)(out + (size_t)row * ND + col) =
                    make_float2(acc[f][g][2 * half] + bv.x,
                                acc[f][g][2 * half + 1] + bv.y);
            }
        }
    }
}

// ---------------------------------------------------------------------------
// GEMM2 experts: grid (8, 24, 4), z = expert. Full K=4096.
// P_e = w_be * (h[e+1] @ W2[e+1]^T + eb2[e])  -> weighted fp16 partial
// ---------------------------------------------------------------------------
__global__ __launch_bounds__(256, 2)
void gemm2e_kernel(const float* __restrict__ eb2)
{
    const int e = blockIdx.z;
    const int mt = blockIdx.y;
    const int b = mt / 3, seg = mt % 3;
    if (seg_masked(e, seg)) return;
    const float wgt = g_w_be[b * NE + e];
    if (wgt == 0.0f) return;

    extern __shared__ char smem[];
    const uint32_t sbase = smem_to_u32(smem);
    const int tid = threadIdx.x;
    const int m0 = mt * BM;
    const int n0 = blockIdx.x * BN;

    float acc[2][8][4];
    #pragma unroll
    for (int f = 0; f < 2; f++)
        #pragma unroll
        for (int g = 0; g < 8; g++)
            #pragma unroll
            for (int k = 0; k < 4; k++) acc[f][g][k] = 0.0f;

    gemm_mainloop(g_h16 + (size_t)(e + 1) * MTOT * NH + (size_t)m0 * NH,
                  g_w2t + (size_t)(e + 1) * ND * NH + (size_t)n0 * NH,
                  NH, NH, NH, sbase, tid, acc);

    const int wid = tid >> 5, lane = tid & 31;
    const int wm = wid >> 1, wn = wid & 1;
    const int gid = lane >> 2, tig = lane & 3;
    __half* P = g_parteh + (size_t)e * MTOT * ND;
    const float* bias = eb2 + (size_t)e * ND;
    #pragma unroll
    for (int f = 0; f < 2; f++) {
        #pragma unroll
        for (int g = 0; g < 8; g++) {
            const int col = n0 + wn * 64 + g * 8 + 2 * tig;
            const float2 bv = *(const float2*)(bias + col);
            #pragma unroll
            for (int half = 0; half < 2; half++) {
                const int row = m0 + wm * 32 + f * 16 + gid + half * 8;
                float v0 = wgt * (acc[f][g][2 * half]     + bv.x);
                float v1 = wgt * (acc[f][g][2 * half + 1] + bv.y);
                *(__half2*)(P + (size_t)row * ND + col) =
                    __halves2half2(__float2half(v0), __float2half(v1));
            }
        }
    }
}

// ---------------------------------------------------------------------------
// Final reduction: out += sum of active weighted expert slices (RMW).
// 8 values per thread.
// ---------------------------------------------------------------------------
__global__ void reduce_kernel(float* __restrict__ out) {
    size_t i8 = (size_t)blockIdx.x * blockDim.x + threadIdx.x;
    size_t i = i8 * 8;
    int row = (int)(i >> 10);
    int b = row / NL, l = row % NL;
    int seg = l >> 7;

    const uint4* P = (const uint4*)g_parteh;   // 8 halves per uint4
    const size_t S = (size_t)MTOT * ND / 8;    // slice stride in uint4

    float4 o0 = *(float4*)(out + i);
    float4 o1 = *(float4*)(out + i + 4);
    float s[8] = {o0.x, o0.y, o0.z, o0.w, o1.x, o1.y, o1.z, o1.w};

    #pragma unroll
    for (int e = 0; e < 4; e++) {
        if (seg_masked(e, seg)) continue;
        if (g_w_be[b * NE + e] == 0.0f) continue;
        uint4 u = P[(size_t)e * S + i8];
        const __half2* h = (const __half2*)&u;
        #pragma unroll
        for (int j = 0; j < 4; j++) {
            float2 a = __half22float2(h[j]);
            s[2 * j]     += a.x;
            s[2 * j + 1] += a.y;
        }
    }
    *(float4*)(out + i)     = make_float4(s[0], s[1], s[2], s[3]);
    *(float4*)(out + i + 4) = make_float4(s[4], s[5], s[6], s[7]);
}

// ---------------------------------------------------------------------------
// Conversions
// ---------------------------------------------------------------------------
__global__ void convert_x_kernel(const float* __restrict__ x) {
    size_t i4 = (size_t)blockIdx.x * blockDim.x + threadIdx.x;
    const float4 v = ((const float4*)x)[i4];
    ((__half2*)g_x16)[i4 * 2 + 0] =
        __halves2half2(__float2half(v.x), __float2half(v.y));
    ((__half2*)g_x16)[i4 * 2 + 1] =
        __halves2half2(__float2half(v.z), __float2half(v.w));
}

// Batched transpose -> fp16. Matrices [R][C] -> dst[z][C][R], z = bz + zoff.
// grid (C/64, R/64, nz), block (32,8).
__global__ void transpose_f16_kernel(const float* __restrict__ src0,
                                     const float* __restrict__ srcE,
                                     __half* __restrict__ dst, int R, int C,
                                     int zoff) {
    __shared__ float tile[64][65];
    const int z = blockIdx.z + zoff;
    const float* W = (z == 0) ? src0 : srcE + (size_t)(z - 1) * R * C;
    const size_t doff = (size_t)z * R * C;
    const int c0 = blockIdx.x * 64, r0 = blockIdx.y * 64;
    const int tx = threadIdx.x, ty = threadIdx.y;
    #pragma unroll
    for (int i = 0; i < 8; i++) {
        int r = i * 8 + ty;
        const float2 v = *(const float2*)(W + (size_t)(r0 + r) * C + c0 + 2 * tx);
        tile[r][2 * tx] = v.x;
        tile[r][2 * tx + 1] = v.y;
    }
    __syncthreads();
    #pragma unroll
    for (int i = 0; i < 8; i++) {
        int c = i * 8 + ty;
        float v0 = tile[2 * tx][c];
        float v1 = tile[2 * tx + 1][c];
        size_t o = (doff + (size_t)(c0 + c) * R + r0 + 2 * tx) >> 1;
        ((__half2*)dst)[o] = __halves2half2(__float2half(v0), __float2half(v1));
    }
}

// ---------------------------------------------------------------------------
// Gating
// ---------------------------------------------------------------------------
__global__ void gate_sum_kernel(const float* __restrict__ x) {
    int b = blockIdx.x, c = blockIdx.y;
    const float* xb = x + ((size_t)b * NL + c * 32) * ND;
    for (int d = threadIdx.x; d < ND; d += 256) {
        float s = 0.f;
        #pragma unroll 8
        for (int l = 0; l < 32; l++) s += xb[(size_t)l * ND + d];
        g_gpart[b][c][d] = s;
    }
}

__global__ void gate_final_kernel(const float* __restrict__ tc,
                                  const float* __restrict__ gW,
                                  const float* __restrict__ gb,
                                  const float* __restrict__ tmW,
                                  const float* __restrict__ tmb) {
    int b = blockIdx.x;
    int t = threadIdx.x;

    float logit[4] = {0.f, 0.f, 0.f, 0.f};
    float modv[8]  = {0.f, 0.f, 0.f, 0.f, 0.f, 0.f, 0.f, 0.f};

    for (int d = t; d < ND; d += 256) {
        float hs = 0.f, ws = 0.f, ps = 0.f;
        #pragma unroll
        for (int c = 0; c < 4; c++)  hs += g_gpart[b][c][d];
        #pragma unroll
        for (int c = 4; c < 8; c++)  ws += g_gpart[b][c][d];
        #pragma unroll
        for (int c = 8; c < 12; c++) ps += g_gpart[b][c][d];
        float full = (hs + ws + ps) * (1.0f / 384.0f);
        float hp   = (hs + ps) * (1.0f / 256.0f);
        float wp   = (ws + ps) * (1.0f / 256.0f);
        #pragma unroll
        for (int e = 0; e < 4; e++) {
            const float* w = gW + (size_t)e * 3 * ND;
            logit[e] += full * w[d] + hp * w[ND + d] + wp * w[2 * ND + d];
        }
        float v = tc[(size_t)b * ND + d];
        float s = v / (1.0f + expf(-v));
        #pragma unroll
        for (int j = 0; j < 8; j++) modv[j] += s * tmW[(size_t)j * ND + d];
    }

    __shared__ float red[12][256];
    #pragma unroll
    for (int v = 0; v < 4; v++) red[v][t] = logit[v];
    #pragma unroll
    for (int v = 0; v < 8; v++) red[4 + v][t] = modv[v];
    __syncthreads();
    for (int s = 128; s > 0; s >>= 1) {
        if (t < s) {
            #pragma unroll
            for (int v = 0; v < 12; v++) red[v][t] += red[v][t + s];
        }
        __syncthreads();
    }

    if (t == 0) {
        float lg[4];
        #pragma unroll
        for (int e = 0; e < 4; e++) {
            float sc = red[4 + e][0] + tmb[e];
            float sh = red[8 + e][0] + tmb[4 + e];
            lg[e] = (red[e][0] + gb[e]) * (1.0f + sc) + sh;
        }
        float mx = fmaxf(fmaxf(lg[0], lg[1]), fmaxf(lg[2], lg[3]));
        float ex[4], sum = 0.f;
        #pragma unroll
        for (int e = 0; e < 4; e++) { ex[e] = expf(lg[e] - mx); sum += ex[e]; }
        float sc4[4];
        #pragma unroll
        for (int e = 0; e < 4; e++) sc4[e] = ex[e] / sum;
        int i1 = 0;
        for (int e = 1; e < 4; e++) if (sc4[e] > sc4[i1]) i1 = e;
        int i2 = -1;
        for (int e = 0; e < 4; e++) {
            if (e == i1) continue;
            if (i2 < 0 || sc4[e] > sc4[i2]) i2 = e;
        }
        float denom = sc4[i1] + sc4[i2] + 1e-8f;
        #pragma unroll
        for (int e = 0; e < 4; e++) g_w_be[b * 4 + e] = 0.0f;
        g_w_be[b * 4 + i1] = sc4[i1] / denom;
        g_w_be[b * 4 + i2] = sc4[i2] / denom;
    }
}

// ---------------------------------------------------------------------------
// kernel_launch — R13 DAG; gemm2 shared writes out directly (fp32),
// experts write weighted fp16 partials; reduce is a slim RMW.
// ---------------------------------------------------------------------------
extern "C" void kernel_launch(void* const* d_in, const int* in_sizes, int n_in,
                              void* d_out, int out_size)
{
    const float* x    = (const float*)d_in[0];
    const float* tc   = (const float*)d_in[1];
    const float* gW   = (const float*)d_in[2];
    const float* gb   = (const float*)d_in[3];
    const float* tmW  = (const float*)d_in[4];
    const float* tmb  = (const float*)d_in[5];
    const float* eW1  = (const float*)d_in[6];
    const float* eb1  = (const float*)d_in[7];
    const float* eW2  = (const float*)d_in[8];
    const float* eb2  = (const float*)d_in[9];
    const float* sW1  = (const float*)d_in[10];
    const float* sb1  = (const float*)d_in[11];
    const float* sW2  = (const float*)d_in[12];
    const float* sb2  = (const float*)d_in[13];
    float* out = (float*)d_out;

    __half *w1t, *w2t;
    cudaGetSymbolAddress((void**)&w1t, g_w1t);
    cudaGetSymbolAddress((void**)&w2t, g_w2t);

    static bool s_init = false;
    static cudaStream_t s1, s2, s3;
    static cudaEvent_t evRoot, evGate, evW1Tsh, evW1T, evW2T, evG1sh, evG2sh;
    if (!s_init) {
        cudaStreamCreateWithFlags(&s1, cudaStreamNonBlocking);
        cudaStreamCreateWithFlags(&s2, cudaStreamNonBlocking);
        cudaStreamCreateWithFlags(&s3, cudaStreamNonBlocking);
        cudaEventCreateWithFlags(&evRoot,  cudaEventDisableTiming);
        cudaEventCreateWithFlags(&evGate,  cudaEventDisableTiming);
        cudaEventCreateWithFlags(&evW1Tsh, cudaEventDisableTiming);
        cudaEventCreateWithFlags(&evW1T,   cudaEventDisableTiming);
        cudaEventCreateWithFlags(&evW2T,   cudaEventDisableTiming);
        cudaEventCreateWithFlags(&evG1sh,  cudaEventDisableTiming);
        cudaEventCreateWithFlags(&evG2sh,  cudaEventDisableTiming);
        cudaFuncSetAttribute(gemm1_kernel,
            cudaFuncAttributeMaxDynamicSharedMemorySize, SMEM_GEMM);
        cudaFuncSetAttribute(gemm2s_kernel,
            cudaFuncAttributeMaxDynamicSharedMemorySize, SMEM_GEMM);
        cudaFuncSetAttribute(gemm2e_kernel,
            cudaFuncAttributeMaxDynamicSharedMemorySize, SMEM_GEMM);
        s_init = true;
    }

    cudaEventRecord(evRoot, 0);
    cudaStreamWaitEvent(s1, evRoot, 0);
    cudaStreamWaitEvent(s2, evRoot, 0);
    cudaStreamWaitEvent(s3, evRoot, 0);

    // main: x -> fp16
    convert_x_kernel<<<(MTOT * ND) / (256 * 4), 256>>>(x);
    // s1: gate chain
    gate_sum_kernel<<<dim3(NB, 12), 256, 0, s1>>>(x);
    gate_final_kernel<<<NB, 256, 0, s1>>>(tc, gW, gb, tmW, tmb);
    cudaEventRecord(evGate, s1);
    // s2: W1 transposes — shared slice first, then experts
    transpose_f16_kernel<<<dim3(NH / 64, ND / 64, 1), dim3(32, 8), 0, s2>>>(
        sW1, eW1, w1t, ND, NH, 0);
    cudaEventRecord(evW1Tsh, s2);
    transpose_f16_kernel<<<dim3(NH / 64, ND / 64, 4), dim3(32, 8), 0, s2>>>(
        sW1, eW1, w1t, ND, NH, 1);
    cudaEventRecord(evW1T, s2);
    // s3: W2 transposes (whole batch; not on critical path)
    transpose_f16_kernel<<<dim3(ND / 64, NH / 64, 5), dim3(32, 8), 0, s3>>>(
        sW2, eW2, w2t, NH, ND, 0);
    cudaEventRecord(evW2T, s3);

    // gemm1 shared (z=0): needs convert (in-stream) + W1T shared slice
    cudaStreamWaitEvent(0, evW1Tsh, 0);
    gemm1_kernel<<<dim3(NH / BN, MTOT / BM, 1), 256, SMEM_GEMM>>>(sb1, eb1, 0);
    cudaEventRecord(evG1sh, 0);

    // gemm2 shared on s2: needs gemm1_sh + W2T — writes out directly
    cudaStreamWaitEvent(s2, evG1sh, 0);
    cudaStreamWaitEvent(s2, evW2T, 0);
    gemm2s_kernel<<<dim3(ND / BN, MTOT / BM), 256, SMEM_GEMM, s2>>>(out, sb2);
    cudaEventRecord(evG2sh, s2);

    // gemm1 experts (z=1..4): needs gate + expert W1T — concurrent w/ gemm2_sh
    cudaStreamWaitEvent(0, evGate, 0);
    cudaStreamWaitEvent(0, evW1T, 0);
    gemm1_kernel<<<dim3(NH / BN, MTOT / BM, 4), 256, SMEM_GEMM>>>(sb1, eb1, 1);

    // gemm2 experts: needs gemm1_exp (in-stream) + W2T
    cudaStreamWaitEvent(0, evW2T, 0);
    gemm2e_kernel<<<dim3(ND / BN, MTOT / BM, 4), 256, SMEM_GEMM>>>(eb2);

    // reduce (RMW on out): needs gemm2_exp (in-stream) + gemm2_sh
    cudaStreamWaitEvent(0, evG2sh, 0);
    reduce_kernel<<<(MTOT * ND) / (256 * 8), 256>>>(out);
}

// round 17
// speedup vs baseline: 1.0464x; 1.0464x over previous
#include <cuda_runtime.h>
#include <cuda_fp16.h>
#include <cstdint>
#include <math.h>

// Problem constants
#define NB 8
#define NL 384
#define ND 1024
#define NE 4
#define NH 4096
#define MTOT (NB * NL)   // 3072 tokens

// ---------------------------------------------------------------------------
// Device scratch (static; no runtime allocation)
// ---------------------------------------------------------------------------
__device__ float g_w_be[NB * NE];
__device__ float g_gpart[NB][12][ND];

__device__ __align__(16) __half g_x16[(size_t)MTOT * ND];

// 5 h slabs (shared + 4 experts), fp16
__device__ __align__(16) __half g_h16[(size_t)5 * MTOT * NH];

// Expert GEMM2 weighted partials: 8 slices (4 experts x 2 K-halves), fp16
__device__ __align__(16) __half g_parteh[(size_t)8 * MTOT * ND];

// Transposed weights fp16: W1T [5][4096][1024], W2T [5][1024][4096]
__device__ __align__(16) __half g_w1t[(size_t)5 * NH * ND];
__device__ __align__(16) __half g_w2t[(size_t)5 * ND * NH];

// ---------------------------------------------------------------------------
// PTX helpers (sm_80+ target-independent)
// ---------------------------------------------------------------------------
__device__ __forceinline__ uint32_t smem_to_u32(const void* p) {
    uint32_t a;
    asm("{ .reg .u64 t; cvta.to.shared.u64 t, %1; cvt.u32.u64 %0, t; }"
        : "=r"(a) : "l"(p));
    return a;
}
__device__ __forceinline__ void cp_async16(uint32_t dst, const void* src) {
    asm volatile("cp.async.cg.shared.global [%0], [%1], 16;"
                 :: "r"(dst), "l"(src));
}
#define CP_COMMIT() asm volatile("cp.async.commit_group;" ::: "memory")
#define CP_WAIT(n)  asm volatile("cp.async.wait_group %0;" :: "n"(n) : "memory")

#define LDSM_X4(r, addr) \
    asm volatile("ldmatrix.sync.aligned.m8n8.x4.shared.b16 {%0,%1,%2,%3}, [%4];" \
        : "=r"((r)[0]), "=r"((r)[1]), "=r"((r)[2]), "=r"((r)[3]) \
        : "r"(addr))

#define MMA_F16(d, a, b) \
    asm volatile("mma.sync.aligned.m16n8k16.row.col.f32.f16.f16.f32 " \
        "{%0,%1,%2,%3}, {%4,%5,%6,%7}, {%8,%9}, {%0,%1,%2,%3};" \
        : "+f"((d)[0]), "+f"((d)[1]), "+f"((d)[2]), "+f"((d)[3]) \
        : "r"((a)[0]), "r"((a)[1]), "r"((a)[2]), "r"((a)[3]), \
          "r"((b)[0]), "r"((b)[1]))

__device__ __forceinline__ float gelu_tanh(float x) {
    float x3 = x * x * x;
    return 0.5f * x * (1.0f + tanhf(0.7978845608028654f * (x + 0.044715f * x3)));
}
// 128B-row SMEM swizzle (Swizzle<3,4,3>): chunk16 ^= row&7
__device__ __forceinline__ uint32_t sw128(uint32_t off) {
    return off ^ ((off >> 3) & 0x70u);
}
__device__ __forceinline__ bool seg_masked(int e, int seg) {
    return (e == 1 && seg == 1) || (e == 2 && seg == 0);
}

// ---------------------------------------------------------------------------
// GEMM core (fp16 single-pass): 128x128 CTA, BK=64, 3-stage cp.async,
// 8 warps (4m x 2n), warp tile 32x64. Stage = A | B, 128x64 fp16 each
// (128B rows, SW128). 4 k16-steps per stage; one barrier per stage.
// ---------------------------------------------------------------------------
#define BM 128
#define BN 128
#define BK 64
#define SUB_BYTES 16384                   // 128 rows x 128B
#define STAGE_BYTES (2 * SUB_BYTES)       // 32KB
#define SMEM_GEMM (3 * STAGE_BYTES)       // 96KB

__device__ __forceinline__ void gemm_mainloop(
    const __half* __restrict__ A, const __half* __restrict__ B,
    int ldA, int ldB, int Klen,
    uint32_t sbase, int tid, float acc[2][8][4])
{
    const int wid  = tid >> 5;
    const int lane = tid & 31;
    const int wm   = wid >> 1;   // 0..3
    const int wn   = wid & 1;    // 0..1
    const int nc = Klen / BK;

    // loader: per subtile 128 rows x 8 chunks(16B) = 1024 chunks; 4/thread
    auto load_stage = [&](int kt, int s) {
        const uint32_t sb = sbase + s * STAGE_BYTES;
        #pragma unroll
        for (int t = 0; t < 2; t++) {
            const int ld = (t == 0) ? ldA : ldB;
            const __half* src = ((t == 0) ? A : B) + kt;
            #pragma unroll
            for (int i = 0; i < 4; i++) {
                int idx = tid + 256 * i;          // 0..1023
                int row = idx >> 3, ch = idx & 7;
                uint32_t off = sw128((uint32_t)(row * 128 + ch * 16));
                cp_async16(sb + t * SUB_BYTES + off,
                           src + (size_t)row * ld + ch * 8);
            }
        }
        CP_COMMIT();
    };

    // ldmatrix coords (row stride 128B)
    const int q = lane >> 3;
    const int a_row  = wm * 32 + (q & 1) * 8 + (lane & 7);
    const int a_colb = (q >> 1) * 16;
    const int b_row  = wn * 64 + (q >> 1) * 8 + (lane & 7);
    const int b_colb = (q & 1) * 16;

    uint32_t a_fr[2][4];
    auto ldsm_a = [&](int s, int ks) {
        const uint32_t sb = sbase + s * STAGE_BYTES;
        #pragma unroll
        for (int f = 0; f < 2; f++) {
            uint32_t off = sw128((uint32_t)((a_row + f * 16) * 128 + ks * 32 + a_colb));
            LDSM_X4(a_fr[f], sb + off);
        }
    };
    auto mma_b = [&](int s, int ks) {
        const uint32_t sb = sbase + s * STAGE_BYTES;
        #pragma unroll
        for (int g2 = 0; g2 < 4; g2++) {
            uint32_t off = sw128((uint32_t)((b_row + g2 * 16) * 128 + ks * 32 + b_colb));
            uint32_t rh[4];
            LDSM_X4(rh, sb + SUB_BYTES + off);
            uint32_t bh0[2] = {rh[0], rh[1]}, bh1[2] = {rh[2], rh[3]};
            MMA_F16(acc[0][2 * g2],     a_fr[0], bh0);
            MMA_F16(acc[0][2 * g2 + 1], a_fr[0], bh1);
            MMA_F16(acc[1][2 * g2],     a_fr[1], bh0);
            MMA_F16(acc[1][2 * g2 + 1], a_fr[1], bh1);
        }
    };

    load_stage(0, 0);
    load_stage(BK, 1);
    for (int c = 0; c < nc; c++) {
        if (c + 1 < nc) { CP_WAIT(1); } else { CP_WAIT(0); }
        __syncthreads();
        const int s = c % 3;
        ldsm_a(s, 0);
        if (c + 2 < nc) load_stage((c + 2) * BK, (c + 2) % 3);
        mma_b(s, 0);
        ldsm_a(s, 1);
        mma_b(s, 1);
        ldsm_a(s, 2);
        mma_b(s, 2);
        ldsm_a(s, 3);
        mma_b(s, 3);
    }
}

// ---------------------------------------------------------------------------
// GEMM1: grid (32, 24, nz), z = blockIdx.z + zoff. z=0 shared, z=e+1 expert.
// h[z] = gelu(x @ W1[z]^T + b1) -> fp16 slab.
// ---------------------------------------------------------------------------
__global__ __launch_bounds__(256, 2)
void gemm1_kernel(const float* __restrict__ sb1,
                  const float* __restrict__ eb1,
                  int zoff)
{
    const int z = blockIdx.z + zoff;
    const int mt = blockIdx.y;
    if (z > 0) {
        int e = z - 1, b = mt / 3, seg = mt % 3;
        if (seg_masked(e, seg)) return;
        if (g_w_be[b * NE + e] == 0.0f) return;
    }
    extern __shared__ char smem[];
    const uint32_t sbase = smem_to_u32(smem);
    const int tid = threadIdx.x;
    const int m0 = mt * BM;
    const int n0 = blockIdx.x * BN;

    const float* bias = (z == 0) ? sb1 : eb1 + (size_t)(z - 1) * NH;

    float acc[2][8][4];
    #pragma unroll
    for (int f = 0; f < 2; f++)
        #pragma unroll
        for (int g = 0; g < 8; g++)
            #pragma unroll
            for (int k = 0; k < 4; k++) acc[f][g][k] = 0.0f;

    gemm_mainloop(g_x16 + (size_t)m0 * ND,
                  g_w1t + (size_t)z * NH * ND + (size_t)n0 * ND,
                  ND, ND, ND, sbase, tid, acc);

    const int wid = tid >> 5, lane = tid & 31;
    const int wm = wid >> 1, wn = wid & 1;
    const int gid = lane >> 2, tig = lane & 3;
    __half* C = g_h16 + (size_t)z * MTOT * NH;
    #pragma unroll
    for (int f = 0; f < 2; f++) {
        #pragma unroll
        for (int g = 0; g < 8; g++) {
            const int col = n0 + wn * 64 + g * 8 + 2 * tig;
            const float2 bv = *(const float2*)(bias + col);
            #pragma unroll
            for (int half = 0; half < 2; half++) {
                const int row = m0 + wm * 32 + f * 16 + gid + half * 8;
                float v0 = gelu_tanh(acc[f][g][2 * half]     + bv.x);
                float v1 = gelu_tanh(acc[f][g][2 * half + 1] + bv.y);
                size_t o = ((size_t)row * NH + col) >> 1;
                ((__half2*)C)[o] = __halves2half2(__float2half(v0),
                                                  __float2half(v1));
            }
        }
    }
}

// ---------------------------------------------------------------------------
// GEMM2 shared path: grid (8, 24). Full K=4096.
// out = h[0] @ W2[0]^T + sb2   (direct fp32 write, overlapped with gemm1_exp)
// ---------------------------------------------------------------------------
__global__ __launch_bounds__(256, 2)
void gemm2s_kernel(float* __restrict__ out, const float* __restrict__ sb2)
{
    extern __shared__ char smem[];
    const uint32_t sbase = smem_to_u32(smem);
    const int tid = threadIdx.x;
    const int m0 = blockIdx.y * BM;
    const int n0 = blockIdx.x * BN;

    float acc[2][8][4];
    #pragma unroll
    for (int f = 0; f < 2; f++)
        #pragma unroll
        for (int g = 0; g < 8; g++)
            #pragma unroll
            for (int k = 0; k < 4; k++) acc[f][g][k] = 0.0f;

    gemm_mainloop(g_h16 + (size_t)m0 * NH,
                  g_w2t + (size_t)n0 * NH,
                  NH, NH, NH, sbase, tid, acc);

    const int wid = tid >> 5, lane = tid & 31;
    const int wm = wid >> 1, wn = wid & 1;
    const int gid = lane >> 2, tig = lane & 3;
    #pragma unroll
    for (int f = 0; f < 2; f++) {
        #pragma unroll
        for (int g = 0; g < 8; g++) {
            const int col = n0 + wn * 64 + g * 8 + 2 * tig;
            const float2 bv = *(const float2*)(sb2 + col);
            #pragma unroll
            for (int half = 0; half < 2; half++) {
                const int row = m0 + wm * 32 + f * 16 + gid + half * 8;
                *(float2*)(out + (size_t)row * ND + col) =
                    make_float2(acc[f][g][2 * half] + bv.x,
                                acc[f][g][2 * half + 1] + bv.y);
            }
        }
    }
}

// ---------------------------------------------------------------------------
// GEMM2 experts (split-K 2): grid (8, 24, 8), z -> (e = z>>1, kh = z&1).
// P[z] = wgt * (h[e+1] @ W2[e+1]^T over K-half  (+ eb2[e] if kh==0))
// ---------------------------------------------------------------------------
__global__ __launch_bounds__(256, 2)
void gemm2e_kernel(const float* __restrict__ eb2)
{
    const int z = blockIdx.z;
    const int e = z >> 1, kh = z & 1;
    const int mt = blockIdx.y;
    const int b = mt / 3, seg = mt % 3;
    if (seg_masked(e, seg)) return;
    const float wgt = g_w_be[b * NE + e];
    if (wgt == 0.0f) return;

    extern __shared__ char smem[];
    const uint32_t sbase = smem_to_u32(smem);
    const int tid = threadIdx.x;
    const int m0 = mt * BM;
    const int n0 = blockIdx.x * BN;
    const int k0 = kh * (NH / 2);

    float acc[2][8][4];
    #pragma unroll
    for (int f = 0; f < 2; f++)
        #pragma unroll
        for (int g = 0; g < 8; g++)
            #pragma unroll
            for (int k = 0; k < 4; k++) acc[f][g][k] = 0.0f;

    gemm_mainloop(g_h16 + (size_t)(e + 1) * MTOT * NH + (size_t)m0 * NH + k0,
                  g_w2t + (size_t)(e + 1) * ND * NH + (size_t)n0 * NH + k0,
                  NH, NH, NH / 2, sbase, tid, acc);

    const int wid = tid >> 5, lane = tid & 31;
    const int wm = wid >> 1, wn = wid & 1;
    const int gid = lane >> 2, tig = lane & 3;
    __half* P = g_parteh + (size_t)z * MTOT * ND;
    const float* bias = eb2 + (size_t)e * ND;
    #pragma unroll
    for (int f = 0; f < 2; f++) {
        #pragma unroll
        for (int g = 0; g < 8; g++) {
            const int col = n0 + wn * 64 + g * 8 + 2 * tig;
            float2 bv = make_float2(0.f, 0.f);
            if (kh == 0) bv = *(const float2*)(bias + col);
            #pragma unroll
            for (int half = 0; half < 2; half++) {
                const int row = m0 + wm * 32 + f * 16 + gid + half * 8;
                float v0 = wgt * (acc[f][g][2 * half]     + bv.x);
                float v1 = wgt * (acc[f][g][2 * half + 1] + bv.y);
                *(__half2*)(P + (size_t)row * ND + col) =
                    __halves2half2(__float2half(v0), __float2half(v1));
            }
        }
    }
}

// ---------------------------------------------------------------------------
// Final reduction: out += sum of active weighted expert slice pairs (RMW).
// 8 values per thread.
// ---------------------------------------------------------------------------
__global__ void reduce_kernel(float* __restrict__ out) {
    size_t i8 = (size_t)blockIdx.x * blockDim.x + threadIdx.x;
    size_t i = i8 * 8;
    int row = (int)(i >> 10);
    int b = row / NL, l = row % NL;
    int seg = l >> 7;

    const uint4* P = (const uint4*)g_parteh;   // 8 halves per uint4
    const size_t S = (size_t)MTOT * ND / 8;    // slice stride in uint4

    float4 o0 = *(float4*)(out + i);
    float4 o1 = *(float4*)(out + i + 4);
    float s[8] = {o0.x, o0.y, o0.z, o0.w, o1.x, o1.y, o1.z, o1.w};

    #pragma unroll
    for (int e = 0; e < 4; e++) {
        if (seg_masked(e, seg)) continue;
        if (g_w_be[b * NE + e] == 0.0f) continue;
        uint4 u0 = P[(size_t)(2 * e) * S + i8];
        uint4 u1 = P[(size_t)(2 * e + 1) * S + i8];
        const __half2* h0 = (const __half2*)&u0;
        const __half2* h1 = (const __half2*)&u1;
        #pragma unroll
        for (int j = 0; j < 4; j++) {
            float2 a = __half22float2(h0[j]);
            float2 c = __half22float2(h1[j]);
            s[2 * j]     += a.x + c.x;
            s[2 * j + 1] += a.y + c.y;
        }
    }
    *(float4*)(out + i)     = make_float4(s[0], s[1], s[2], s[3]);
    *(float4*)(out + i + 4) = make_float4(s[4], s[5], s[6], s[7]);
}

// ---------------------------------------------------------------------------
// Conversions
// ---------------------------------------------------------------------------
__global__ void convert_x_kernel(const float* __restrict__ x) {
    size_t i4 = (size_t)blockIdx.x * blockDim.x + threadIdx.x;
    const float4 v = ((const float4*)x)[i4];
    ((__half2*)g_x16)[i4 * 2 + 0] =
        __halves2half2(__float2half(v.x), __float2half(v.y));
    ((__half2*)g_x16)[i4 * 2 + 1] =
        __halves2half2(__float2half(v.z), __float2half(v.w));
}

// Batched transpose -> fp16. Matrices [R][C] -> dst[z][C][R], z = bz + zoff.
// grid (C/64, R/64, nz), block (32,8).
__global__ void transpose_f16_kernel(const float* __restrict__ src0,
                                     const float* __restrict__ srcE,
                                     __half* __restrict__ dst, int R, int C,
                                     int zoff) {
    __shared__ float tile[64][65];
    const int z = blockIdx.z + zoff;
    const float* W = (z == 0) ? src0 : srcE + (size_t)(z - 1) * R * C;
    const size_t doff = (size_t)z * R * C;
    const int c0 = blockIdx.x * 64, r0 = blockIdx.y * 64;
    const int tx = threadIdx.x, ty = threadIdx.y;
    #pragma unroll
    for (int i = 0; i < 8; i++) {
        int r = i * 8 + ty;
        const float2 v = *(const float2*)(W + (size_t)(r0 + r) * C + c0 + 2 * tx);
        tile[r][2 * tx] = v.x;
        tile[r][2 * tx + 1] = v.y;
    }
    __syncthreads();
    #pragma unroll
    for (int i = 0; i < 8; i++) {
        int c = i * 8 + ty;
        float v0 = tile[2 * tx][c];
        float v1 = tile[2 * tx + 1][c];
        size_t o = (doff + (size_t)(c0 + c) * R + r0 + 2 * tx) >> 1;
        ((__half2*)dst)[o] = __halves2half2(__float2half(v0), __float2half(v1));
    }
}

// ---------------------------------------------------------------------------
// Gating
// ---------------------------------------------------------------------------
__global__ void gate_sum_kernel(const float* __restrict__ x) {
    int b = blockIdx.x, c = blockIdx.y;
    const float* xb = x + ((size_t)b * NL + c * 32) * ND;
    for (int d = threadIdx.x; d < ND; d += 256) {
        float s = 0.f;
        #pragma unroll 8
        for (int l = 0; l < 32; l++) s += xb[(size_t)l * ND + d];
        g_gpart[b][c][d] = s;
    }
}

__global__ void gate_final_kernel(const float* __restrict__ tc,
                                  const float* __restrict__ gW,
                                  const float* __restrict__ gb,
                                  const float* __restrict__ tmW,
                                  const float* __restrict__ tmb) {
    int b = blockIdx.x;
    int t = threadIdx.x;

    float logit[4] = {0.f, 0.f, 0.f, 0.f};
    float modv[8]  = {0.f, 0.f, 0.f, 0.f, 0.f, 0.f, 0.f, 0.f};

    for (int d = t; d < ND; d += 256) {
        float hs = 0.f, ws = 0.f, ps = 0.f;
        #pragma unroll
        for (int c = 0; c < 4; c++)  hs += g_gpart[b][c][d];
        #pragma unroll
        for (int c = 4; c < 8; c++)  ws += g_gpart[b][c][d];
        #pragma unroll
        for (int c = 8; c < 12; c++) ps += g_gpart[b][c][d];
        float full = (hs + ws + ps) * (1.0f / 384.0f);
        float hp   = (hs + ps) * (1.0f / 256.0f);
        float wp   = (ws + ps) * (1.0f / 256.0f);
        #pragma unroll
        for (int e = 0; e < 4; e++) {
            const float* w = gW + (size_t)e * 3 * ND;
            logit[e] += full * w[d] + hp * w[ND + d] + wp * w[2 * ND + d];
        }
        float v = tc[(size_t)b * ND + d];
        float s = v / (1.0f + expf(-v));
        #pragma unroll
        for (int j = 0; j < 8; j++) modv[j] += s * tmW[(size_t)j * ND + d];
    }

    __shared__ float red[12][256];
    #pragma unroll
    for (int v = 0; v < 4; v++) red[v][t] = logit[v];
    #pragma unroll
    for (int v = 0; v < 8; v++) red[4 + v][t] = modv[v];
    __syncthreads();
    for (int s = 128; s > 0; s >>= 1) {
        if (t < s) {
            #pragma unroll
            for (int v = 0; v < 12; v++) red[v][t] += red[v][t + s];
        }
        __syncthreads();
    }

    if (t == 0) {
        float lg[4];
        #pragma unroll
        for (int e = 0; e < 4; e++) {
            float sc = red[4 + e][0] + tmb[e];
            float sh = red[8 + e][0] + tmb[4 + e];
            lg[e] = (red[e][0] + gb[e]) * (1.0f + sc) + sh;
        }
        float mx = fmaxf(fmaxf(lg[0], lg[1]), fmaxf(lg[2], lg[3]));
        float ex[4], sum = 0.f;
        #pragma unroll
        for (int e = 0; e < 4; e++) { ex[e] = expf(lg[e] - mx); sum += ex[e]; }
        float sc4[4];
        #pragma unroll
        for (int e = 0; e < 4; e++) sc4[e] = ex[e] / sum;
        int i1 = 0;
        for (int e = 1; e < 4; e++) if (sc4[e] > sc4[i1]) i1 = e;
        int i2 = -1;
        for (int e = 0; e < 4; e++) {
            if (e == i1) continue;
            if (i2 < 0 || sc4[e] > sc4[i2]) i2 = e;
        }
        float denom = sc4[i1] + sc4[i2] + 1e-8f;
        #pragma unroll
        for (int e = 0; e < 4; e++) g_w_be[b * 4 + e] = 0.0f;
        g_w_be[b * 4 + i1] = sc4[i1] / denom;
        g_w_be[b * 4 + i2] = sc4[i2] / denom;
    }
}

// ---------------------------------------------------------------------------
// kernel_launch — R13 DAG; shared gemm2 writes out directly (fp32, full K,
// overlapped); expert gemm2 split-K=2 with weighted fp16 partials; slim RMW
// reduce.
// ---------------------------------------------------------------------------
extern "C" void kernel_launch(void* const* d_in, const int* in_sizes, int n_in,
                              void* d_out, int out_size)
{
    const float* x    = (const float*)d_in[0];
    const float* tc   = (const float*)d_in[1];
    const float* gW   = (const float*)d_in[2];
    const float* gb   = (const float*)d_in[3];
    const float* tmW  = (const float*)d_in[4];
    const float* tmb  = (const float*)d_in[5];
    const float* eW1  = (const float*)d_in[6];
    const float* eb1  = (const float*)d_in[7];
    const float* eW2  = (const float*)d_in[8];
    const float* eb2  = (const float*)d_in[9];
    const float* sW1  = (const float*)d_in[10];
    const float* sb1  = (const float*)d_in[11];
    const float* sW2  = (const float*)d_in[12];
    const float* sb2  = (const float*)d_in[13];
    float* out = (float*)d_out;

    __half *w1t, *w2t;
    cudaGetSymbolAddress((void**)&w1t, g_w1t);
    cudaGetSymbolAddress((void**)&w2t, g_w2t);

    static bool s_init = false;
    static cudaStream_t s1, s2, s3;
    static cudaEvent_t evRoot, evGate, evW1Tsh, evW1T, evW2T, evG1sh, evG2sh;
    if (!s_init) {
        cudaStreamCreateWithFlags(&s1, cudaStreamNonBlocking);
        cudaStreamCreateWithFlags(&s2, cudaStreamNonBlocking);
        cudaStreamCreateWithFlags(&s3, cudaStreamNonBlocking);
        cudaEventCreateWithFlags(&evRoot,  cudaEventDisableTiming);
        cudaEventCreateWithFlags(&evGate,  cudaEventDisableTiming);
        cudaEventCreateWithFlags(&evW1Tsh, cudaEventDisableTiming);
        cudaEventCreateWithFlags(&evW1T,   cudaEventDisableTiming);
        cudaEventCreateWithFlags(&evW2T,   cudaEventDisableTiming);
        cudaEventCreateWithFlags(&evG1sh,  cudaEventDisableTiming);
        cudaEventCreateWithFlags(&evG2sh,  cudaEventDisableTiming);
        cudaFuncSetAttribute(gemm1_kernel,
            cudaFuncAttributeMaxDynamicSharedMemorySize, SMEM_GEMM);
        cudaFuncSetAttribute(gemm2s_kernel,
            cudaFuncAttributeMaxDynamicSharedMemorySize, SMEM_GEMM);
        cudaFuncSetAttribute(gemm2e_kernel,
            cudaFuncAttributeMaxDynamicSharedMemorySize, SMEM_GEMM);
        s_init = true;
    }

    cudaEventRecord(evRoot, 0);
    cudaStreamWaitEvent(s1, evRoot, 0);
    cudaStreamWaitEvent(s2, evRoot, 0);
    cudaStreamWaitEvent(s3, evRoot, 0);

    // main: x -> fp16
    convert_x_kernel<<<(MTOT * ND) / (256 * 4), 256>>>(x);
    // s1: gate chain
    gate_sum_kernel<<<dim3(NB, 12), 256, 0, s1>>>(x);
    gate_final_kernel<<<NB, 256, 0, s1>>>(tc, gW, gb, tmW, tmb);
    cudaEventRecord(evGate, s1);
    // s2: W1 transposes — shared slice first, then experts
    transpose_f16_kernel<<<dim3(NH / 64, ND / 64, 1), dim3(32, 8), 0, s2>>>(
        sW1, eW1, w1t, ND, NH, 0);
    cudaEventRecord(evW1Tsh, s2);
    transpose_f16_kernel<<<dim3(NH / 64, ND / 64, 4), dim3(32, 8), 0, s2>>>(
        sW1, eW1, w1t, ND, NH, 1);
    cudaEventRecord(evW1T, s2);
    // s3: W2 transposes (whole batch; not on critical path)
    transpose_f16_kernel<<<dim3(ND / 64, NH / 64, 5), dim3(32, 8), 0, s3>>>(
        sW2, eW2, w2t, NH, ND, 0);
    cudaEventRecord(evW2T, s3);

    // gemm1 shared (z=0): needs convert (in-stream) + W1T shared slice
    cudaStreamWaitEvent(0, evW1Tsh, 0);
    gemm1_kernel<<<dim3(NH / BN, MTOT / BM, 1), 256, SMEM_GEMM>>>(sb1, eb1, 0);
    cudaEventRecord(evG1sh, 0);

    // gemm2 shared on s2: needs gemm1_sh + W2T — writes out directly
    cudaStreamWaitEvent(s2, evG1sh, 0);
    cudaStreamWaitEvent(s2, evW2T, 0);
    gemm2s_kernel<<<dim3(ND / BN, MTOT / BM), 256, SMEM_GEMM, s2>>>(out, sb2);
    cudaEventRecord(evG2sh, s2);

    // gemm1 experts (z=1..4): needs gate + expert W1T — concurrent w/ gemm2_sh
    cudaStreamWaitEvent(0, evGate, 0);
    cudaStreamWaitEvent(0, evW1T, 0);
    gemm1_kernel<<<dim3(NH / BN, MTOT / BM, 4), 256, SMEM_GEMM>>>(sb1, eb1, 1);

    // gemm2 experts (split-K 2, 8 z-slices): needs gemm1_exp (in-stream) + W2T
    cudaStreamWaitEvent(0, evW2T, 0);
    gemm2e_kernel<<<dim3(ND / BN, MTOT / BM, 8), 256, SMEM_GEMM>>>(eb2);

    // reduce (RMW on out): needs gemm2_exp (in-stream) + gemm2_sh
    cudaStreamWaitEvent(0, evG2sh, 0);
    reduce_kernel<<<(MTOT * ND) / (256 * 8), 256>>>(out);
}